// round 2
// baseline (speedup 1.0000x reference)
#include <cuda_runtime.h>
#include <cstdint>

// Problem constants
#define BATCH 4
#define NPIX  4096      // 64*64 after space-to-depth
#define CDIM  256       // c * s * s
#define CQ    32        // CDIM / 8
#define HW    64        // H=W after s2d
#define S2    2

// Scratch (allocation-free rule: __device__ globals)
__device__ float g_q[(size_t)BATCH * NPIX * CQ];
__device__ float g_k[(size_t)BATCH * NPIX * CQ];
__device__ float g_v[(size_t)BATCH * NPIX * CDIM];
__device__ float g_o[(size_t)BATCH * NPIX * CDIM];

// ---------------------------------------------------------------------------
// Kernel 1: fused space-to-depth + Q/K/V 1x1-conv projections.
// xp[b, CC, h2, w2] = x[b, ci, 2*h2+hi, 2*w2+wi],  CC = wi*128 + hi*64 + ci.
// Each block: one (b, h2, whalf) -> 32 pixels. xs[pixel][CC] staged in smem.
// ---------------------------------------------------------------------------
__global__ __launch_bounds__(256) void proj_kernel(
    const float* __restrict__ x,
    const float* __restrict__ wq, const float* __restrict__ bq,
    const float* __restrict__ wk, const float* __restrict__ bk,
    const float* __restrict__ wv, const float* __restrict__ bv)
{
    __shared__ float xs[32][260];   // 32 pixels x 256 channels (pad 260 -> f4-aligned)
    const int whalf = blockIdx.x;   // 0..1
    const int h2    = blockIdx.y;   // 0..63
    const int b     = blockIdx.z;   // 0..3
    const int t     = threadIdx.x;

    // Load 128 source rows (ci,hi) x 64 w-contiguous floats, scatter to xs.
    #pragma unroll
    for (int i = 0; i < 32; i++) {
        int idx = i * 256 + t;          // 0..8191
        int row = idx >> 6;             // 0..127 = hi*64 + ci
        int j   = idx & 63;             // w offset within half-row
        int ci  = row & 63;
        int hi  = row >> 6;
        float val = x[(((size_t)(b * 64 + ci) * 128) + (2 * h2 + hi)) * 128
                      + whalf * 64 + j];
        int p  = j >> 1;
        int wi = j & 1;
        int CC = wi * 128 + hi * 64 + ci;
        xs[p][CC] = val;
    }
    __syncthreads();

    const int lane = t & 31;
    const int wid  = t >> 5;
    const int n    = h2 * 64 + whalf * 32 + lane;   // pixel index
    const float4* x4 = (const float4*)(&xs[lane][0]);  // lane stride 260 floats (16B aligned)

    // Each warp computes 40 of the 320 outputs for all 32 pixels (lane=pixel).
    for (int o = wid * 40; o < wid * 40 + 40; o++) {
        const float* wrow;
        float bias;
        float* dst;
        if (o < 32)      { wrow = wq + o * 256;        bias = bq[o];
                           dst = g_q + ((size_t)(b * NPIX + n)) * CQ + o; }
        else if (o < 64) { wrow = wk + (o - 32) * 256; bias = bk[o - 32];
                           dst = g_k + ((size_t)(b * NPIX + n)) * CQ + (o - 32); }
        else             { wrow = wv + (o - 64) * 256; bias = bv[o - 64];
                           dst = g_v + ((size_t)(b * NPIX + n)) * CDIM + (o - 64); }
        const float4* w4 = (const float4*)wrow;   // broadcast across warp
        float acc = bias;
        #pragma unroll 8
        for (int c4 = 0; c4 < 64; c4++) {
            float4 w = w4[c4];
            float4 xv = x4[c4];
            acc += w.x * xv.x + w.y * xv.y + w.z * xv.z + w.w * xv.w;
        }
        *dst = acc;
    }
}

// ---------------------------------------------------------------------------
// Kernel 2: flash attention, fp32.  BM = BN = 64, d_qk = 32, d_v = 256.
// Block = 256 threads: thread t owns row r = t&63, column block cb = t>>6
// (64 cols). Q row in registers, acc[64] in registers.
// S stored transposed St[j][r] -> conflict-free P reads; V reads broadcast.
// ---------------------------------------------------------------------------
#define SM_KS   0                 // 64*32   = 2048 floats
#define SM_VS   2048              // 64*260  = 16640 floats (f4 rows of 65)
#define SM_ST   (2048 + 16640)    // 64*64   = 4096 floats
#define SM_M    (SM_ST + 4096)    // 64
#define SM_L    (SM_M + 64)       // 64
#define SM_F    (SM_L + 64)       // 64
#define SM_RED  (SM_F + 64)       // 256
#define SM_TOT  (SM_RED + 256)    // 23232 floats = 92928 bytes

__global__ __launch_bounds__(256, 2) void attn_kernel()
{
    extern __shared__ float sm[];
    float* Ks  = sm + SM_KS;
    float* Vs  = sm + SM_VS;
    float* St  = sm + SM_ST;
    float* m_s = sm + SM_M;
    float* l_s = sm + SM_L;
    float* fct = sm + SM_F;
    float* red = sm + SM_RED;

    const int b  = blockIdx.y;
    const int n0 = blockIdx.x * 64;
    const int t  = threadIdx.x;
    const int r  = t & 63;
    const int cb = t >> 6;

    // Q row -> registers (4 threads share a row; L1 broadcast)
    float qreg[32];
    {
        const float4* qsrc = (const float4*)(g_q + ((size_t)(b * NPIX + n0 + r)) * CQ);
        #pragma unroll
        for (int i = 0; i < 8; i++) {
            float4 v = qsrc[i];
            qreg[4 * i + 0] = v.x; qreg[4 * i + 1] = v.y;
            qreg[4 * i + 2] = v.z; qreg[4 * i + 3] = v.w;
        }
    }

    float acc[64];
    #pragma unroll
    for (int c = 0; c < 64; c++) acc[c] = 0.0f;

    if (t < 64) { m_s[t] = -1e30f; l_s[t] = 0.0f; }

    for (int m0 = 0; m0 < NPIX; m0 += 64) {
        __syncthreads();   // protects Ks/Vs/St reuse (and first-iter m/l init)

        // cooperative loads: K tile (512 f4), V tile (4096 f4, padded rows)
        {
            const float4* ksrc = (const float4*)(g_k + ((size_t)(b * NPIX + m0)) * CQ);
            float4* Ks4 = (float4*)Ks;
            Ks4[t]       = ksrc[t];
            Ks4[t + 256] = ksrc[t + 256];
            const float4* vsrc = (const float4*)(g_v + ((size_t)(b * NPIX + m0)) * CDIM);
            float4* Vs4 = (float4*)Vs;
            #pragma unroll
            for (int i = 0; i < 16; i++) {
                int g  = i * 256 + t;
                int j  = g >> 6;
                int c4 = g & 63;
                Vs4[j * 65 + c4] = vsrc[g];
            }
        }
        __syncthreads();

        // S = Q K^T  (store transposed), per-thread 16 j values
        float pmax = -1e30f;
        #pragma unroll
        for (int jj = 0; jj < 16; jj++) {
            int j = cb * 16 + jj;
            const float4* krow = (const float4*)(Ks + j * 32);  // broadcast
            float s = 0.0f;
            #pragma unroll
            for (int c4 = 0; c4 < 8; c4++) {
                float4 kv = krow[c4];
                s += kv.x * qreg[4 * c4 + 0] + kv.y * qreg[4 * c4 + 1]
                   + kv.z * qreg[4 * c4 + 2] + kv.w * qreg[4 * c4 + 3];
            }
            St[j * 64 + r] = s;
            pmax = fmaxf(pmax, s);
        }
        red[cb * 64 + r] = pmax;
        __syncthreads();

        if (t < 64) {
            float M = fmaxf(fmaxf(red[t], red[64 + t]),
                            fmaxf(red[128 + t], red[192 + t]));
            float Mnew = fmaxf(m_s[t], M);
            fct[t] = __expf(m_s[t] - Mnew);
            m_s[t] = Mnew;
        }
        __syncthreads();

        // P = exp(S - m), partial row sums, rescale acc
        const float mrow = m_s[r];
        float psum = 0.0f;
        #pragma unroll
        for (int jj = 0; jj < 16; jj++) {
            int j = cb * 16 + jj;
            float p = __expf(St[j * 64 + r] - mrow);
            St[j * 64 + r] = p;
            psum += p;
        }
        red[cb * 64 + r] = psum;
        const float f = fct[r];
        #pragma unroll
        for (int c = 0; c < 64; c++) acc[c] *= f;
        __syncthreads();

        if (t < 64)
            l_s[t] = l_s[t] * fct[t] + red[t] + red[64 + t] + red[128 + t] + red[192 + t];

        // acc += P @ V   (V broadcast LDS128, pure-FFMA bound)
        #pragma unroll 2
        for (int j = 0; j < 64; j++) {
            float p = St[j * 64 + r];
            const float4* vrow = (const float4*)(Vs + j * 260 + cb * 64);
            #pragma unroll
            for (int c4 = 0; c4 < 16; c4++) {
                float4 v4 = vrow[c4];
                acc[c4 * 4 + 0] += p * v4.x;
                acc[c4 * 4 + 1] += p * v4.y;
                acc[c4 * 4 + 2] += p * v4.z;
                acc[c4 * 4 + 3] += p * v4.w;
            }
        }
    }
    __syncthreads();

    // normalize, stage through Vs, write coalesced
    const float linv = 1.0f / l_s[r];
    {
        float4* Vs4 = (float4*)Vs;
        #pragma unroll
        for (int c4 = 0; c4 < 16; c4++) {
            float4 o4;
            o4.x = acc[c4 * 4 + 0] * linv;
            o4.y = acc[c4 * 4 + 1] * linv;
            o4.z = acc[c4 * 4 + 2] * linv;
            o4.w = acc[c4 * 4 + 3] * linv;
            Vs4[r * 65 + cb * 16 + c4] = o4;
        }
    }
    __syncthreads();
    {
        float4* odst = (float4*)(g_o + ((size_t)(b * NPIX + n0)) * CDIM);
        float4* Vs4 = (float4*)Vs;
        #pragma unroll
        for (int i = 0; i < 16; i++) {
            int g  = i * 256 + t;
            int j  = g >> 6;
            int c4 = g & 63;
            odst[g] = Vs4[j * 65 + c4];
        }
    }
}

// ---------------------------------------------------------------------------
// Kernel 3: epilogue = gamma * out + xp, then depth-to-space, fp32 out.
// Coalesced on x read and final write.
// ---------------------------------------------------------------------------
__global__ __launch_bounds__(256) void epi_kernel(
    const float* __restrict__ x, const float* __restrict__ gamma,
    float* __restrict__ out)
{
    int idx = blockIdx.x * 256 + threadIdx.x;     // over 4*64*128*128
    int w  = idx & 127;
    int h  = (idx >> 7) & 127;
    int ci = (idx >> 14) & 63;
    int b  = idx >> 20;
    int h2 = h >> 1, hi = h & 1;
    int w2 = w >> 1, wi = w & 1;
    int CC = wi * 128 + hi * 64 + ci;
    int n  = h2 * 64 + w2;
    float g = __ldg(gamma);
    out[idx] = g * g_o[((size_t)(b * NPIX + n)) * CDIM + CC] + x[idx];
}

// ---------------------------------------------------------------------------
extern "C" void kernel_launch(void* const* d_in, const int* in_sizes, int n_in,
                              void* d_out, int out_size)
{
    const float* x     = (const float*)d_in[0];
    const float* wq    = (const float*)d_in[1];
    const float* bq    = (const float*)d_in[2];
    const float* wk    = (const float*)d_in[3];
    const float* bk    = (const float*)d_in[4];
    const float* wv    = (const float*)d_in[5];
    const float* bv    = (const float*)d_in[6];
    const float* gamma = (const float*)d_in[7];
    float* out = (float*)d_out;

    (void)in_sizes; (void)n_in; (void)out_size;

    // opt-in to >48KB dynamic smem (idempotent; not a stream op, capture-safe)
    cudaFuncSetAttribute(attn_kernel,
                         cudaFuncAttributeMaxDynamicSharedMemorySize,
                         SM_TOT * (int)sizeof(float));

    dim3 pgrid(2, 64, BATCH);
    proj_kernel<<<pgrid, 256>>>(x, wq, bq, wk, bk, wv, bv);

    dim3 agrid(NPIX / 64, BATCH);
    attn_kernel<<<agrid, 256, SM_TOT * sizeof(float)>>>();

    epi_kernel<<<(BATCH * 64 * 128 * 128) / 256, 256>>>(x, gamma, out);
}

// round 5
// speedup vs baseline: 1.0015x; 1.0015x over previous
#include <cuda_runtime.h>
#include <cstdint>

// Problem constants
#define BATCH 4
#define NPIX  4096      // 64*64 after space-to-depth
#define CDIM  256       // c * s * s
#define CQ    32        // CDIM / 8
#define HW    64        // H=W after s2d
#define S2    2

// Scratch (allocation-free rule: __device__ globals)
__device__ float g_q[(size_t)BATCH * NPIX * CQ];
__device__ float g_k[(size_t)BATCH * NPIX * CQ];
__device__ float g_v[(size_t)BATCH * NPIX * CDIM];
__device__ float g_o[(size_t)BATCH * NPIX * CDIM];

// ---------------------------------------------------------------------------
// Kernel 1: fused space-to-depth + Q/K/V 1x1-conv projections.
// xp[b, CC, h2, w2] = x[b, ci, 2*h2+hi, 2*w2+wi],  CC = wi*128 + hi*64 + ci.
// Each block: one (b, h2, whalf) -> 32 pixels. xs[pixel][CC] staged in smem.
// ---------------------------------------------------------------------------
__global__ __launch_bounds__(256) void proj_kernel(
    const float* __restrict__ x,
    const float* __restrict__ wq, const float* __restrict__ bq,
    const float* __restrict__ wk, const float* __restrict__ bk,
    const float* __restrict__ wv, const float* __restrict__ bv)
{
    __shared__ float xs[32][260];   // 32 pixels x 256 channels (pad 260 -> f4-aligned)
    const int whalf = blockIdx.x;   // 0..1
    const int h2    = blockIdx.y;   // 0..63
    const int b     = blockIdx.z;   // 0..3
    const int t     = threadIdx.x;

    // Load 128 source rows (ci,hi) x 64 w-contiguous floats, scatter to xs.
    #pragma unroll
    for (int i = 0; i < 32; i++) {
        int idx = i * 256 + t;          // 0..8191
        int row = idx >> 6;             // 0..127 = hi*64 + ci
        int j   = idx & 63;             // w offset within half-row
        int ci  = row & 63;
        int hi  = row >> 6;
        float val = x[(((size_t)(b * 64 + ci) * 128) + (2 * h2 + hi)) * 128
                      + whalf * 64 + j];
        int p  = j >> 1;
        int wi = j & 1;
        int CC = wi * 128 + hi * 64 + ci;
        xs[p][CC] = val;
    }
    __syncthreads();

    const int lane = t & 31;
    const int wid  = t >> 5;
    const int n    = h2 * 64 + whalf * 32 + lane;   // pixel index
    const float4* x4 = (const float4*)(&xs[lane][0]);  // lane stride 260 floats (16B aligned)

    // Each warp computes 40 of the 320 outputs for all 32 pixels (lane=pixel).
    for (int o = wid * 40; o < wid * 40 + 40; o++) {
        const float* wrow;
        float bias;
        float* dst;
        if (o < 32)      { wrow = wq + o * 256;        bias = bq[o];
                           dst = g_q + ((size_t)(b * NPIX + n)) * CQ + o; }
        else if (o < 64) { wrow = wk + (o - 32) * 256; bias = bk[o - 32];
                           dst = g_k + ((size_t)(b * NPIX + n)) * CQ + (o - 32); }
        else             { wrow = wv + (o - 64) * 256; bias = bv[o - 64];
                           dst = g_v + ((size_t)(b * NPIX + n)) * CDIM + (o - 64); }
        const float4* w4 = (const float4*)wrow;   // broadcast across warp
        float acc = bias;
        #pragma unroll 8
        for (int c4 = 0; c4 < 64; c4++) {
            float4 w = w4[c4];
            float4 xv = x4[c4];
            acc += w.x * xv.x + w.y * xv.y + w.z * xv.z + w.w * xv.w;
        }
        *dst = acc;
    }
}

// ---------------------------------------------------------------------------
// Kernel 2: flash attention, fp32.  BM = BN = 64, d_qk = 32, d_v = 256.
// Block = 256 threads: thread t owns row r = t&63, column block cb = t>>6
// (64 cols). Q row in registers, acc[64] in registers.
// S stored transposed St[j][r] -> conflict-free P reads; V reads broadcast.
// ---------------------------------------------------------------------------
#define SM_KS   0                 // 64*32   = 2048 floats
#define SM_VS   2048              // 64*260  = 16640 floats (f4 rows of 65)
#define SM_ST   (2048 + 16640)    // 64*64   = 4096 floats
#define SM_M    (SM_ST + 4096)    // 64
#define SM_L    (SM_M + 64)       // 64
#define SM_F    (SM_L + 64)       // 64
#define SM_RED  (SM_F + 64)       // 256
#define SM_TOT  (SM_RED + 256)    // 23232 floats = 92928 bytes

__global__ __launch_bounds__(256, 2) void attn_kernel()
{
    extern __shared__ float sm[];
    float* Ks  = sm + SM_KS;
    float* Vs  = sm + SM_VS;
    float* St  = sm + SM_ST;
    float* m_s = sm + SM_M;
    float* l_s = sm + SM_L;
    float* fct = sm + SM_F;
    float* red = sm + SM_RED;

    const int b  = blockIdx.y;
    const int n0 = blockIdx.x * 64;
    const int t  = threadIdx.x;
    const int r  = t & 63;
    const int cb = t >> 6;

    // Q row -> registers (4 threads share a row; L1 broadcast)
    float qreg[32];
    {
        const float4* qsrc = (const float4*)(g_q + ((size_t)(b * NPIX + n0 + r)) * CQ);
        #pragma unroll
        for (int i = 0; i < 8; i++) {
            float4 v = qsrc[i];
            qreg[4 * i + 0] = v.x; qreg[4 * i + 1] = v.y;
            qreg[4 * i + 2] = v.z; qreg[4 * i + 3] = v.w;
        }
    }

    float acc[64];
    #pragma unroll
    for (int c = 0; c < 64; c++) acc[c] = 0.0f;

    if (t < 64) { m_s[t] = -1e30f; l_s[t] = 0.0f; }

    for (int m0 = 0; m0 < NPIX; m0 += 64) {
        __syncthreads();   // protects Ks/Vs/St reuse (and first-iter m/l init)

        // cooperative loads: K tile (512 f4), V tile (4096 f4, padded rows)
        {
            const float4* ksrc = (const float4*)(g_k + ((size_t)(b * NPIX + m0)) * CQ);
            float4* Ks4 = (float4*)Ks;
            Ks4[t]       = ksrc[t];
            Ks4[t + 256] = ksrc[t + 256];
            const float4* vsrc = (const float4*)(g_v + ((size_t)(b * NPIX + m0)) * CDIM);
            float4* Vs4 = (float4*)Vs;
            #pragma unroll
            for (int i = 0; i < 16; i++) {
                int g  = i * 256 + t;
                int j  = g >> 6;
                int c4 = g & 63;
                Vs4[j * 65 + c4] = vsrc[g];
            }
        }
        __syncthreads();

        // S = Q K^T  (store transposed), per-thread 16 j values
        float pmax = -1e30f;
        #pragma unroll
        for (int jj = 0; jj < 16; jj++) {
            int j = cb * 16 + jj;
            const float4* krow = (const float4*)(Ks + j * 32);  // broadcast
            float s = 0.0f;
            #pragma unroll
            for (int c4 = 0; c4 < 8; c4++) {
                float4 kv = krow[c4];
                s += kv.x * qreg[4 * c4 + 0] + kv.y * qreg[4 * c4 + 1]
                   + kv.z * qreg[4 * c4 + 2] + kv.w * qreg[4 * c4 + 3];
            }
            St[j * 64 + r] = s;
            pmax = fmaxf(pmax, s);
        }
        red[cb * 64 + r] = pmax;
        __syncthreads();

        if (t < 64) {
            float M = fmaxf(fmaxf(red[t], red[64 + t]),
                            fmaxf(red[128 + t], red[192 + t]));
            float Mnew = fmaxf(m_s[t], M);
            fct[t] = __expf(m_s[t] - Mnew);
            m_s[t] = Mnew;
        }
        __syncthreads();

        // P = exp(S - m), partial row sums, rescale acc
        const float mrow = m_s[r];
        float psum = 0.0f;
        #pragma unroll
        for (int jj = 0; jj < 16; jj++) {
            int j = cb * 16 + jj;
            float p = __expf(St[j * 64 + r] - mrow);
            St[j * 64 + r] = p;
            psum += p;
        }
        red[cb * 64 + r] = psum;
        const float f = fct[r];
        #pragma unroll
        for (int c = 0; c < 64; c++) acc[c] *= f;
        __syncthreads();

        if (t < 64)
            l_s[t] = l_s[t] * fct[t] + red[t] + red[64 + t] + red[128 + t] + red[192 + t];

        // acc += P @ V   (V broadcast LDS128, pure-FFMA bound)
        #pragma unroll 2
        for (int j = 0; j < 64; j++) {
            float p = St[j * 64 + r];
            const float4* vrow = (const float4*)(Vs + j * 260 + cb * 64);
            #pragma unroll
            for (int c4 = 0; c4 < 16; c4++) {
                float4 v4 = vrow[c4];
                acc[c4 * 4 + 0] += p * v4.x;
                acc[c4 * 4 + 1] += p * v4.y;
                acc[c4 * 4 + 2] += p * v4.z;
                acc[c4 * 4 + 3] += p * v4.w;
            }
        }
    }
    __syncthreads();

    // normalize, stage through Vs, write coalesced
    const float linv = 1.0f / l_s[r];
    {
        float4* Vs4 = (float4*)Vs;
        #pragma unroll
        for (int c4 = 0; c4 < 16; c4++) {
            float4 o4;
            o4.x = acc[c4 * 4 + 0] * linv;
            o4.y = acc[c4 * 4 + 1] * linv;
            o4.z = acc[c4 * 4 + 2] * linv;
            o4.w = acc[c4 * 4 + 3] * linv;
            Vs4[r * 65 + cb * 16 + c4] = o4;
        }
    }
    __syncthreads();
    {
        float4* odst = (float4*)(g_o + ((size_t)(b * NPIX + n0)) * CDIM);
        float4* Vs4 = (float4*)Vs;
        #pragma unroll
        for (int i = 0; i < 16; i++) {
            int g  = i * 256 + t;
            int j  = g >> 6;
            int c4 = g & 63;
            odst[g] = Vs4[j * 65 + c4];
        }
    }
}

// ---------------------------------------------------------------------------
// Kernel 3: epilogue = gamma * out + xp, then depth-to-space, fp32 out.
// Coalesced on x read and final write.
// ---------------------------------------------------------------------------
__global__ __launch_bounds__(256) void epi_kernel(
    const float* __restrict__ x, const float* __restrict__ gamma,
    float* __restrict__ out)
{
    int idx = blockIdx.x * 256 + threadIdx.x;     // over 4*64*128*128
    int w  = idx & 127;
    int h  = (idx >> 7) & 127;
    int ci = (idx >> 14) & 63;
    int b  = idx >> 20;
    int h2 = h >> 1, hi = h & 1;
    int w2 = w >> 1, wi = w & 1;
    int CC = wi * 128 + hi * 64 + ci;
    int n  = h2 * 64 + w2;
    float g = __ldg(gamma);
    out[idx] = g * g_o[((size_t)(b * NPIX + n)) * CDIM + CC] + x[idx];
}

// ---------------------------------------------------------------------------
extern "C" void kernel_launch(void* const* d_in, const int* in_sizes, int n_in,
                              void* d_out, int out_size)
{
    const float* x     = (const float*)d_in[0];
    const float* wq    = (const float*)d_in[1];
    const float* bq    = (const float*)d_in[2];
    const float* wk    = (const float*)d_in[3];
    const float* bk    = (const float*)d_in[4];
    const float* wv    = (const float*)d_in[5];
    const float* bv    = (const float*)d_in[6];
    const float* gamma = (const float*)d_in[7];
    float* out = (float*)d_out;

    (void)in_sizes; (void)n_in; (void)out_size;

    // opt-in to >48KB dynamic smem (idempotent; not a stream op, capture-safe)
    cudaFuncSetAttribute(attn_kernel,
                         cudaFuncAttributeMaxDynamicSharedMemorySize,
                         SM_TOT * (int)sizeof(float));

    dim3 pgrid(2, 64, BATCH);
    proj_kernel<<<pgrid, 256>>>(x, wq, bq, wk, bk, wv, bv);

    dim3 agrid(NPIX / 64, BATCH);
    attn_kernel<<<agrid, 256, SM_TOT * sizeof(float)>>>();

    epi_kernel<<<(BATCH * 64 * 128 * 128) / 256, 256>>>(x, gamma, out);
}

// round 8
// speedup vs baseline: 6.1305x; 6.1213x over previous
#include <cuda_runtime.h>
#include <cuda_bf16.h>
#include <cstdint>

#define BATCH 4
#define NPIX  4096
#define CDIM  256

// Scratch (__device__ globals; allocation-free rule)
__device__ __nv_bfloat16 g_q64[(size_t)BATCH * NPIX * 64];   // [qh(32)|ql(32)]
__device__ __nv_bfloat16 g_k64[(size_t)BATCH * NPIX * 64];   // [kh(32)|kl(32)]
__device__ __nv_bfloat16 g_v  [(size_t)BATCH * NPIX * CDIM]; // V [b][m][c] bf16
__device__ __nv_bfloat16 g_P  [(size_t)BATCH * NPIX * NPIX]; // e^(E-40) bf16
__device__ float         g_l  [BATCH * NPIX];                // row sums
__device__ float         g_o  [(size_t)BATCH * NPIX * CDIM]; // attention out

// ---------------- helpers ----------------
__device__ __forceinline__ uint32_t s2u(const void* p) {
    uint32_t a;
    asm("{ .reg .u64 t; cvta.to.shared.u64 t, %1; cvt.u32.u64 %0, t; }" : "=r"(a) : "l"(p));
    return a;
}
// packs (e0, e1) -> bf16x2 word, e0 in low half
__device__ __forceinline__ uint32_t packbf(float e0, float e1) {
    uint32_t r;
    asm("cvt.rn.satfinite.bf16x2.f32 %0, %1, %2;" : "=r"(r) : "f"(e1), "f"(e0));
    return r;
}
__device__ __forceinline__ void ldsm4(uint32_t* r, uint32_t a) {
    asm volatile("ldmatrix.sync.aligned.m8n8.x4.shared.b16 {%0,%1,%2,%3}, [%4];"
                 : "=r"(r[0]), "=r"(r[1]), "=r"(r[2]), "=r"(r[3]) : "r"(a));
}
__device__ __forceinline__ void ldsm4t(uint32_t* r, uint32_t a) {
    asm volatile("ldmatrix.sync.aligned.m8n8.x4.trans.shared.b16 {%0,%1,%2,%3}, [%4];"
                 : "=r"(r[0]), "=r"(r[1]), "=r"(r[2]), "=r"(r[3]) : "r"(a));
}
__device__ __forceinline__ void mma16816(float* d, const uint32_t* a, uint32_t b0, uint32_t b1) {
    asm volatile("mma.sync.aligned.m16n8k16.row.col.f32.bf16.bf16.f32 "
                 "{%0,%1,%2,%3}, {%4,%5,%6,%7}, {%8,%9}, {%0,%1,%2,%3};"
                 : "+f"(d[0]), "+f"(d[1]), "+f"(d[2]), "+f"(d[3])
                 : "r"(a[0]), "r"(a[1]), "r"(a[2]), "r"(a[3]), "r"(b0), "r"(b1));
}
__device__ __forceinline__ void cpa16(uint32_t dst, const void* src) {
    asm volatile("cp.async.cg.shared.global [%0], [%1], 16;" :: "r"(dst), "l"(src) : "memory");
}
#define CP_COMMIT() asm volatile("cp.async.commit_group;" ::: "memory")

// ---------------------------------------------------------------------------
// Kernel 1: space-to-depth + Q/K/V projections, register-tiled 10x4.
// Emits [qh|ql], [kh|kl] 64-bf16 rows and V[m][c] bf16.
// ---------------------------------------------------------------------------
#define PROJ_SMEM ((32 * 260 + 320 * 33) * 4)

__global__ __launch_bounds__(256) void proj_kernel(
    const float* __restrict__ x,
    const float* __restrict__ wq, const float* __restrict__ bq,
    const float* __restrict__ wk, const float* __restrict__ bk,
    const float* __restrict__ wv, const float* __restrict__ bv)
{
    extern __shared__ float psm[];
    float* xs  = psm;              // [32][260]
    float* osm = psm + 32 * 260;   // [320][33]
    const int whalf = blockIdx.x, h2 = blockIdx.y, b = blockIdx.z;
    const int t = threadIdx.x;

    // zero row-sum buffer for this graph replay
    int gid = (((b * 64 + h2) * 2 + whalf) << 8) + t;
    if (gid < BATCH * NPIX) g_l[gid] = 0.0f;

    #pragma unroll
    for (int i = 0; i < 32; i++) {
        int idx = i * 256 + t;
        int row = idx >> 6, j = idx & 63;
        int ci = row & 63, hi = row >> 6;
        float val = x[(((size_t)(b * 64 + ci) * 128) + (2 * h2 + hi)) * 128 + whalf * 64 + j];
        xs[(j >> 1) * 260 + (j & 1) * 128 + hi * 64 + ci] = val;
    }
    __syncthreads();

    const int lane = t & 31, w = t >> 5;
    const int og = lane >> 3, pg = lane & 7;
    const int wbase = w * 40;

    const float4* wr[10]; float bias[10];
    #pragma unroll
    for (int j = 0; j < 10; j++) {
        int o = wbase + og * 10 + j;
        if (o < 32)      { wr[j] = (const float4*)(wq + o * 256);        bias[j] = bq[o]; }
        else if (o < 64) { wr[j] = (const float4*)(wk + (o - 32) * 256); bias[j] = bk[o - 32]; }
        else             { wr[j] = (const float4*)(wv + (o - 64) * 256); bias[j] = bv[o - 64]; }
    }
    float acc[10][4];
    #pragma unroll
    for (int j = 0; j < 10; j++)
        #pragma unroll
        for (int i = 0; i < 4; i++) acc[j][i] = bias[j];

    const float4* xs4 = (const float4*)xs;
    #pragma unroll 2
    for (int c4 = 0; c4 < 64; c4++) {
        float4 xv[4];
        #pragma unroll
        for (int i = 0; i < 4; i++) xv[i] = xs4[(pg + 8 * i) * 65 + c4];
        #pragma unroll
        for (int j = 0; j < 10; j++) {
            float4 wv4 = wr[j][c4];
            #pragma unroll
            for (int i = 0; i < 4; i++)
                acc[j][i] += wv4.x * xv[i].x + wv4.y * xv[i].y
                           + wv4.z * xv[i].z + wv4.w * xv[i].w;
        }
    }
    #pragma unroll
    for (int j = 0; j < 10; j++) {
        int o = wbase + og * 10 + j;
        #pragma unroll
        for (int i = 0; i < 4; i++) osm[o * 33 + pg + 8 * i] = acc[j][i];
    }
    __syncthreads();

    const int n0 = h2 * 64 + whalf * 32;
    const int p = t >> 3, cg = t & 7;

    // Q/K writer: 4 channels per (p, cg); hi|lo split
    {
        size_t rowoff = ((size_t)(b * NPIX + n0 + p)) * 64;
        #pragma unroll
        for (int qk = 0; qk < 2; qk++) {
            float v0 = osm[(qk * 32 + cg * 4 + 0) * 33 + p];
            float v1 = osm[(qk * 32 + cg * 4 + 1) * 33 + p];
            float v2 = osm[(qk * 32 + cg * 4 + 2) * 33 + p];
            float v3 = osm[(qk * 32 + cg * 4 + 3) * 33 + p];
            float h0 = __bfloat162float(__float2bfloat16(v0));
            float h1 = __bfloat162float(__float2bfloat16(v1));
            float h2f = __bfloat162float(__float2bfloat16(v2));
            float h3 = __bfloat162float(__float2bfloat16(v3));
            uint32_t* dst = (uint32_t*)((qk == 0 ? g_q64 : g_k64) + rowoff);
            dst[cg * 2]          = packbf(h0, h1);
            dst[cg * 2 + 1]      = packbf(h2f, h3);
            dst[16 + cg * 2]     = packbf(v0 - h0, v1 - h1);
            dst[16 + cg * 2 + 1] = packbf(v2 - h2f, v3 - h3);
        }
    }
    // V writer: 32 channels (cg*32..) of pixel p, contiguous
    {
        uint4* vdst = (uint4*)(g_v + ((size_t)(b * NPIX + n0 + p)) * CDIM + cg * 32);
        #pragma unroll
        for (int i = 0; i < 4; i++) {
            int c0 = 64 + cg * 32 + i * 8;   // osm row index of channel
            uint4 u;
            u.x = packbf(osm[(c0 + 0) * 33 + p], osm[(c0 + 1) * 33 + p]);
            u.y = packbf(osm[(c0 + 2) * 33 + p], osm[(c0 + 3) * 33 + p]);
            u.z = packbf(osm[(c0 + 4) * 33 + p], osm[(c0 + 5) * 33 + p]);
            u.w = packbf(osm[(c0 + 6) * 33 + p], osm[(c0 + 7) * 33 + p]);
            vdst[i] = u;
        }
    }
}

// ---------------------------------------------------------------------------
// Kernel 2: E = QK^T (compensated bf16 HMMA) + fused exp(E-40) -> P, row sums.
// CTA: 128 n-rows x 128 m-cols. 8 warps: warp_r (64 rows) x warp_c (32 cols).
// ---------------------------------------------------------------------------
__global__ __launch_bounds__(256, 2) void egemm_kernel()
{
    __shared__ __align__(16) __nv_bfloat16 esm[2 * 128 * 72];  // sQ | sK, reused as P stage
    __nv_bfloat16* sQ = esm;
    __nv_bfloat16* sK = esm + 128 * 72;
    const int m0 = blockIdx.x * 128, n0 = blockIdx.y * 128, b = blockIdx.z;
    const int t = threadIdx.x, lane = t & 31, wid = t >> 5;
    const int warp_r = wid >> 2, warp_c = wid & 3;

    {
        const uint4* qs = (const uint4*)(g_q64 + ((size_t)(b * NPIX + n0)) * 64);
        const uint4* ks = (const uint4*)(g_k64 + ((size_t)(b * NPIX + m0)) * 64);
        uint4* q4 = (uint4*)sQ;
        uint4* k4 = (uint4*)sK;
        #pragma unroll
        for (int i = 0; i < 4; i++) {
            int idx = i * 256 + t;
            int row = idx >> 3, ch = idx & 7;
            q4[row * 9 + ch] = qs[idx];
            k4[row * 9 + ch] = ks[idx];
        }
    }
    __syncthreads();

    float acc[4][4][4];
    #pragma unroll
    for (int mi = 0; mi < 4; mi++)
        #pragma unroll
        for (int ni = 0; ni < 4; ni++)
            #pragma unroll
            for (int i = 0; i < 4; i++) acc[mi][ni][i] = 0.0f;

    #pragma unroll
    for (int prod = 0; prod < 3; prod++) {
        const int aoff = (prod == 1) ? 32 : 0;   // ql
        const int boff = (prod == 2) ? 32 : 0;   // kl
        #pragma unroll
        for (int k16 = 0; k16 < 2; k16++) {
            const int kb = k16 * 16;
            uint32_t A[4][4];
            #pragma unroll
            for (int mi = 0; mi < 4; mi++)
                ldsm4(A[mi], s2u(sQ + (warp_r * 64 + mi * 16 + (lane & 15)) * 72
                                    + aoff + kb + ((lane >> 4) << 3)));
            uint32_t Bm[2][4];
            #pragma unroll
            for (int nj = 0; nj < 2; nj++)
                ldsm4(Bm[nj], s2u(sK + (warp_c * 32 + nj * 16 + (lane & 15)) * 72
                                     + boff + kb + ((lane >> 4) << 3)));
            #pragma unroll
            for (int mi = 0; mi < 4; mi++)
                #pragma unroll
                for (int ni = 0; ni < 4; ni++) {
                    int nj = ni >> 1, s = ni & 1;
                    mma16816(acc[mi][ni], A[mi], Bm[nj][s], Bm[nj][s + 2]);
                }
        }
    }
    __syncthreads();   // sQ/sK dead; reuse as P stage (stride 136 bf16)

    __nv_bfloat16* sS = esm;
    #pragma unroll
    for (int mi = 0; mi < 4; mi++) {
        int r0 = warp_r * 64 + mi * 16 + (lane >> 2);
        #pragma unroll
        for (int ni = 0; ni < 4; ni++) {
            int c = warp_c * 32 + ni * 8 + (lane & 3) * 2;
            float p00 = __expf(acc[mi][ni][0] - 40.0f);
            float p01 = __expf(acc[mi][ni][1] - 40.0f);
            float p10 = __expf(acc[mi][ni][2] - 40.0f);
            float p11 = __expf(acc[mi][ni][3] - 40.0f);
            *(uint32_t*)(sS + r0 * 136 + c)       = packbf(p00, p01);
            *(uint32_t*)(sS + (r0 + 8) * 136 + c) = packbf(p10, p11);
        }
    }
    __syncthreads();

    // coalesced P write + row sums
    #pragma unroll
    for (int pass = 0; pass < 4; pass++) {
        int row = pass * 32 + (t >> 3), ch = t & 7;
        const uint4* srow = (const uint4*)(sS + row * 136);
        uint4 u0 = srow[ch * 2], u1 = srow[ch * 2 + 1];
        float s = 0.0f;
        const uint32_t wv[8] = {u0.x, u0.y, u0.z, u0.w, u1.x, u1.y, u1.z, u1.w};
        #pragma unroll
        for (int i = 0; i < 8; i++) {
            __nv_bfloat162 h = *(const __nv_bfloat162*)&wv[i];
            s += __bfloat162float(h.x) + __bfloat162float(h.y);
        }
        s += __shfl_xor_sync(0xffffffffu, s, 1);
        s += __shfl_xor_sync(0xffffffffu, s, 2);
        s += __shfl_xor_sync(0xffffffffu, s, 4);
        if (ch == 0) atomicAdd(&g_l[b * NPIX + n0 + row], s);
        uint4* drow = (uint4*)(g_P + ((size_t)(b * NPIX + n0 + row)) * NPIX + m0);
        drow[ch * 2] = u0;
        drow[ch * 2 + 1] = u1;
    }
}

// ---------------------------------------------------------------------------
// Kernel 3: O = P @ V  (bf16 HMMA, K=4096 in 64-chunks, cp.async double buffer)
// CTA: 128 n-rows x 256 c-cols. 8 warps: warp_r (64 rows) x warp_c (64 cols).
// ---------------------------------------------------------------------------
#define PBUF (128 * 72)          // bf16
#define VBUF (64 * 264)
#define BUFBF (PBUF + VBUF)
#define PV_SMEM (2 * BUFBF * 2)  // bytes = 104448

__global__ __launch_bounds__(256, 1) void pv_kernel()
{
    extern __shared__ __align__(16) __nv_bfloat16 pvs[];
    const int n0 = blockIdx.x * 128, b = blockIdx.y;
    const int t = threadIdx.x, lane = t & 31, wid = t >> 5;
    const int warp_r = wid >> 2, warp_c = wid & 3;

    const __nv_bfloat16* pbase = g_P + ((size_t)(b * NPIX + n0)) * NPIX;
    const __nv_bfloat16* vbase = g_v + (size_t)b * NPIX * CDIM;

    float acc[4][8][4];
    #pragma unroll
    for (int mi = 0; mi < 4; mi++)
        #pragma unroll
        for (int ni = 0; ni < 8; ni++)
            #pragma unroll
            for (int i = 0; i < 4; i++) acc[mi][ni][i] = 0.0f;

    // issue chunk loads into buffer s
    auto issue = [&](int ch, int s) {
        __nv_bfloat16* sP = pvs + s * BUFBF;
        __nv_bfloat16* sV = sP + PBUF;
        #pragma unroll
        for (int i = 0; i < 4; i++) {
            int idx = i * 256 + t;
            int row = idx >> 3, c8 = idx & 7;
            cpa16(s2u(sP + row * 72 + c8 * 8),
                  pbase + (size_t)row * NPIX + ch * 64 + c8 * 8);
        }
        #pragma unroll
        for (int i = 0; i < 8; i++) {
            int idx = i * 256 + t;
            int row = idx >> 5, c8 = idx & 31;
            cpa16(s2u(sV + row * 264 + c8 * 8),
                  vbase + (size_t)(ch * 64 + row) * CDIM + c8 * 8);
        }
        CP_COMMIT();
    };

    issue(0, 0);
    for (int ch = 0; ch < 64; ch++) {
        if (ch < 63) issue(ch + 1, (ch + 1) & 1);
        if (ch < 63) asm volatile("cp.async.wait_group 1;" ::: "memory");
        else         asm volatile("cp.async.wait_group 0;" ::: "memory");
        __syncthreads();
        __nv_bfloat16* sP = pvs + (ch & 1) * BUFBF;
        __nv_bfloat16* sV = sP + PBUF;
        #pragma unroll
        for (int k16 = 0; k16 < 4; k16++) {
            const int kb = k16 * 16;
            uint32_t A[4][4];
            #pragma unroll
            for (int mi = 0; mi < 4; mi++)
                ldsm4(A[mi], s2u(sP + (warp_r * 64 + mi * 16 + (lane & 15)) * 72
                                    + kb + ((lane >> 4) << 3)));
            uint32_t Bm[4][4];
            #pragma unroll
            for (int nj = 0; nj < 4; nj++) {
                int k = kb + (lane & 7) + ((lane >> 4) << 3);
                int n = warp_c * 64 + nj * 16 + ((lane >> 3) & 1) * 8;
                ldsm4t(Bm[nj], s2u(sV + k * 264 + n));
            }
            #pragma unroll
            for (int mi = 0; mi < 4; mi++)
                #pragma unroll
                for (int ni = 0; ni < 8; ni++) {
                    int nj = ni >> 1, s = ni & 1;
                    mma16816(acc[mi][ni], A[mi], Bm[nj][s], Bm[nj][s + 2]);
                }
        }
        __syncthreads();
    }

    // epilogue: normalize by 1/l, write f32
    #pragma unroll
    for (int mi = 0; mi < 4; mi++) {
        int r0 = n0 + warp_r * 64 + mi * 16 + (lane >> 2);
        float li0 = 1.0f / g_l[b * NPIX + r0];
        float li1 = 1.0f / g_l[b * NPIX + r0 + 8];
        float* o0 = g_o + ((size_t)(b * NPIX + r0)) * CDIM;
        float* o1 = g_o + ((size_t)(b * NPIX + r0 + 8)) * CDIM;
        #pragma unroll
        for (int ni = 0; ni < 8; ni++) {
            int c = warp_c * 64 + ni * 8 + (lane & 3) * 2;
            *(float2*)(o0 + c) = make_float2(acc[mi][ni][0] * li0, acc[mi][ni][1] * li0);
            *(float2*)(o1 + c) = make_float2(acc[mi][ni][2] * li1, acc[mi][ni][3] * li1);
        }
    }
}

// ---------------------------------------------------------------------------
// Kernel 4: epilogue gamma*O + xp, depth-to-space
// ---------------------------------------------------------------------------
__global__ __launch_bounds__(256) void epi_kernel(
    const float* __restrict__ x, const float* __restrict__ gamma,
    float* __restrict__ out)
{
    int idx = blockIdx.x * 256 + threadIdx.x;
    int w = idx & 127, h = (idx >> 7) & 127, ci = (idx >> 14) & 63, b = idx >> 20;
    int CC = (w & 1) * 128 + (h & 1) * 64 + ci;
    int n = (h >> 1) * 64 + (w >> 1);
    out[idx] = __ldg(gamma) * g_o[((size_t)(b * NPIX + n)) * CDIM + CC] + x[idx];
}

// ---------------------------------------------------------------------------
extern "C" void kernel_launch(void* const* d_in, const int* in_sizes, int n_in,
                              void* d_out, int out_size)
{
    const float* x     = (const float*)d_in[0];
    const float* wq    = (const float*)d_in[1];
    const float* bq    = (const float*)d_in[2];
    const float* wk    = (const float*)d_in[3];
    const float* bk    = (const float*)d_in[4];
    const float* wv    = (const float*)d_in[5];
    const float* bv    = (const float*)d_in[6];
    const float* gamma = (const float*)d_in[7];
    float* out = (float*)d_out;
    (void)in_sizes; (void)n_in; (void)out_size;

    cudaFuncSetAttribute(proj_kernel, cudaFuncAttributeMaxDynamicSharedMemorySize, PROJ_SMEM);
    cudaFuncSetAttribute(pv_kernel,   cudaFuncAttributeMaxDynamicSharedMemorySize, PV_SMEM);

    dim3 pgrid(2, 64, BATCH);
    proj_kernel<<<pgrid, 256, PROJ_SMEM>>>(x, wq, bq, wk, bk, wv, bv);

    dim3 egrid(NPIX / 128, NPIX / 128, BATCH);
    egemm_kernel<<<egrid, 256>>>();

    dim3 vgrid(NPIX / 128, BATCH);
    pv_kernel<<<vgrid, 256, PV_SMEM>>>();

    epi_kernel<<<(BATCH * 64 * 128 * 128) / 256, 256>>>(x, gamma, out);
}

// round 9
// speedup vs baseline: 7.6179x; 1.2426x over previous
#include <cuda_runtime.h>
#include <cuda_bf16.h>
#include <cstdint>

#define BATCH 4
#define NPIX  4096
#define CDIM  256
#define NPTOT (BATCH * NPIX)   // 16384 pixels total

// Scratch (__device__ globals; allocation-free rule)
__device__ __nv_bfloat16 g_wh [320 * 256];                  // weights hi
__device__ __nv_bfloat16 g_wl [320 * 256];                  // weights lo
__device__ __nv_bfloat16 g_xh [(size_t)NPTOT * 256];        // xp hi
__device__ __nv_bfloat16 g_xl [(size_t)NPTOT * 256];        // xp lo
__device__ __nv_bfloat16 g_q64[(size_t)NPTOT * 64];         // [qh(32)|ql(32)]
__device__ __nv_bfloat16 g_k64[(size_t)NPTOT * 64];         // [kh(32)|kl(32)]
__device__ __nv_bfloat16 g_v  [(size_t)NPTOT * CDIM];       // V [pg][c] bf16
__device__ __nv_bfloat16 g_P  [(size_t)BATCH * NPIX * NPIX];// e^(E-40) bf16
__device__ float         g_l  [NPTOT];                      // row sums
__device__ float         g_o  [(size_t)BATCH * CDIM * NPIX];// O transposed [b][c][n]

// ---------------- helpers ----------------
__device__ __forceinline__ uint32_t s2u(const void* p) {
    uint32_t a;
    asm("{ .reg .u64 t; cvta.to.shared.u64 t, %1; cvt.u32.u64 %0, t; }" : "=r"(a) : "l"(p));
    return a;
}
// packs (e0, e1) -> bf16x2 word, e0 in low half
__device__ __forceinline__ uint32_t packbf(float e0, float e1) {
    uint32_t r;
    asm("cvt.rn.satfinite.bf16x2.f32 %0, %1, %2;" : "=r"(r) : "f"(e1), "f"(e0));
    return r;
}
__device__ __forceinline__ void ldsm4(uint32_t* r, uint32_t a) {
    asm volatile("ldmatrix.sync.aligned.m8n8.x4.shared.b16 {%0,%1,%2,%3}, [%4];"
                 : "=r"(r[0]), "=r"(r[1]), "=r"(r[2]), "=r"(r[3]) : "r"(a));
}
__device__ __forceinline__ void ldsm4t(uint32_t* r, uint32_t a) {
    asm volatile("ldmatrix.sync.aligned.m8n8.x4.trans.shared.b16 {%0,%1,%2,%3}, [%4];"
                 : "=r"(r[0]), "=r"(r[1]), "=r"(r[2]), "=r"(r[3]) : "r"(a));
}
__device__ __forceinline__ void mma16816(float* d, const uint32_t* a, uint32_t b0, uint32_t b1) {
    asm volatile("mma.sync.aligned.m16n8k16.row.col.f32.bf16.bf16.f32 "
                 "{%0,%1,%2,%3}, {%4,%5,%6,%7}, {%8,%9}, {%0,%1,%2,%3};"
                 : "+f"(d[0]), "+f"(d[1]), "+f"(d[2]), "+f"(d[3])
                 : "r"(a[0]), "r"(a[1]), "r"(a[2]), "r"(a[3]), "r"(b0), "r"(b1));
}
__device__ __forceinline__ void cpa16(uint32_t dst, const void* src) {
    asm volatile("cp.async.cg.shared.global [%0], [%1], 16;" :: "r"(dst), "l"(src) : "memory");
}
#define CP_COMMIT() asm volatile("cp.async.commit_group;" ::: "memory")

// ---------------------------------------------------------------------------
// Kernel 0: weight hi/lo split (one-time, tiny)
// Combined out index o: 0..31 q, 32..63 k, 64..319 v.
// ---------------------------------------------------------------------------
__global__ __launch_bounds__(256) void wconv_kernel(
    const float* __restrict__ wq, const float* __restrict__ wk,
    const float* __restrict__ wv)
{
    #pragma unroll
    for (int i = 0; i < 4; i++) {
        int e = blockIdx.x * 1024 + i * 256 + threadIdx.x;
        int o = e >> 8, c = e & 255;
        const float* src = (o < 32) ? (wq + o * 256)
                         : (o < 64) ? (wk + (o - 32) * 256)
                                    : (wv + (o - 64) * 256);
        float v = src[c];
        float h = __bfloat162float(__float2bfloat16(v));
        g_wh[e] = __float2bfloat16(v);
        g_wl[e] = __float2bfloat16(v - h);
    }
}

// ---------------------------------------------------------------------------
// Kernel 1: space-to-depth gather, emit xp as bf16 hi/lo (row-major [pg][256]).
// Also zeroes g_l for this graph replay.
// ---------------------------------------------------------------------------
__global__ __launch_bounds__(256) void gather_kernel(const float* __restrict__ x)
{
    __shared__ float xs[32][260];
    const int whalf = blockIdx.x, h2 = blockIdx.y, b = blockIdx.z;
    const int t = threadIdx.x;

    int gid = (((b * 64 + h2) * 2 + whalf) << 8) + t;
    if (gid < NPTOT) g_l[gid] = 0.0f;

    #pragma unroll
    for (int i = 0; i < 32; i++) {
        int idx = i * 256 + t;
        int row = idx >> 6, j = idx & 63;
        int ci = row & 63, hi = row >> 6;
        float val = x[(((size_t)(b * 64 + ci) * 128) + (2 * h2 + hi)) * 128 + whalf * 64 + j];
        xs[j >> 1][(j & 1) * 128 + hi * 64 + ci] = val;
    }
    __syncthreads();

    const int p = t >> 3;           // pixel 0..31
    const int cg = t & 7;           // channel pair group
    const size_t pg = (size_t)b * NPIX + h2 * 64 + whalf * 32 + p;
    uint32_t* dh = (uint32_t*)(g_xh + pg * 256);
    uint32_t* dl = (uint32_t*)(g_xl + pg * 256);
    #pragma unroll
    for (int i = 0; i < 16; i++) {
        int u = cg + i * 8;         // u32 index 0..127
        float v0 = xs[p][u * 2], v1 = xs[p][u * 2 + 1];
        float h0 = __bfloat162float(__float2bfloat16(v0));
        float h1 = __bfloat162float(__float2bfloat16(v1));
        dh[u] = packbf(h0, h1);
        dl[u] = packbf(v0 - h0, v1 - h1);
    }
}

// ---------------------------------------------------------------------------
// Kernel 2: projections as compensated bf16 HMMA GEMM.
// CTA: 128 pixels x 64 outputs. Grid (128 pixel tiles, 5 out tiles).
// 8 warps = 2 (px) x 4 (out): warp tile 64 px x 16 out.
// K = 256 in chunks of 32, cp.async double buffered.
// Products: xh*wh + xh*wl + xl*wh.
// ---------------------------------------------------------------------------
#define PG_AS   40                       // A row stride (bf16)
#define PG_ABUF (128 * PG_AS)            // per matrix (bf16)
#define PG_BBUF (64 * PG_AS)
#define PG_STAGE (2 * PG_ABUF + 2 * PG_BBUF)
#define PG_SMEM (2 * PG_STAGE * 2)       // bytes = 61440

__global__ __launch_bounds__(256, 2) void projgemm_kernel(
    const float* __restrict__ bq, const float* __restrict__ bk,
    const float* __restrict__ bv)
{
    extern __shared__ __nv_bfloat16 pgs[];
    const int ptile = blockIdx.x, otile = blockIdx.y;
    const int t = threadIdx.x, lane = t & 31, wid = t >> 5;
    const int warp_r = wid >> 2, warp_o = wid & 3;

    auto issue = [&](int kc, int s) {
        __nv_bfloat16* Ah = pgs + s * PG_STAGE;
        __nv_bfloat16* Al = Ah + PG_ABUF;
        __nv_bfloat16* Bh = Al + PG_ABUF;
        __nv_bfloat16* Bl = Bh + PG_BBUF;
        #pragma unroll
        for (int i = 0; i < 2; i++) {
            int idx = i * 256 + t;
            int row = idx >> 2, c16 = idx & 3;
            size_t src = (size_t)(ptile * 128 + row) * 256 + kc * 32 + c16 * 8;
            cpa16(s2u(Ah + row * PG_AS + c16 * 8), g_xh + src);
            cpa16(s2u(Al + row * PG_AS + c16 * 8), g_xl + src);
        }
        {
            int row = t >> 2, c16 = t & 3;
            size_t src = (size_t)(otile * 64 + row) * 256 + kc * 32 + c16 * 8;
            cpa16(s2u(Bh + row * PG_AS + c16 * 8), g_wh + src);
            cpa16(s2u(Bl + row * PG_AS + c16 * 8), g_wl + src);
        }
        CP_COMMIT();
    };

    float acc[4][2][4];
    #pragma unroll
    for (int mi = 0; mi < 4; mi++)
        #pragma unroll
        for (int ni = 0; ni < 2; ni++)
            #pragma unroll
            for (int i = 0; i < 4; i++) acc[mi][ni][i] = 0.0f;

    issue(0, 0);
    for (int kc = 0; kc < 8; kc++) {
        if (kc < 7) issue(kc + 1, (kc + 1) & 1);
        if (kc < 7) asm volatile("cp.async.wait_group 1;" ::: "memory");
        else        asm volatile("cp.async.wait_group 0;" ::: "memory");
        __syncthreads();
        __nv_bfloat16* Ah = pgs + (kc & 1) * PG_STAGE;
        __nv_bfloat16* Al = Ah + PG_ABUF;
        __nv_bfloat16* Bh = Al + PG_ABUF;
        __nv_bfloat16* Bl = Bh + PG_BBUF;
        #pragma unroll
        for (int k16 = 0; k16 < 2; k16++) {
            const int kb = k16 * 16 + ((lane >> 4) << 3);
            uint32_t Ahf[4][4], Alf[4][4], Bhf[4], Blf[4];
            #pragma unroll
            for (int mi = 0; mi < 4; mi++) {
                int r = warp_r * 64 + mi * 16 + (lane & 15);
                ldsm4(Ahf[mi], s2u(Ah + r * PG_AS + kb));
                ldsm4(Alf[mi], s2u(Al + r * PG_AS + kb));
            }
            {
                int r = warp_o * 16 + (lane & 15);
                ldsm4(Bhf, s2u(Bh + r * PG_AS + kb));
                ldsm4(Blf, s2u(Bl + r * PG_AS + kb));
            }
            #pragma unroll
            for (int mi = 0; mi < 4; mi++)
                #pragma unroll
                for (int ni = 0; ni < 2; ni++) {
                    mma16816(acc[mi][ni], Ahf[mi], Bhf[ni], Bhf[ni + 2]);
                    mma16816(acc[mi][ni], Ahf[mi], Blf[ni], Blf[ni + 2]);
                    mma16816(acc[mi][ni], Alf[mi], Bhf[ni], Bhf[ni + 2]);
                }
        }
        __syncthreads();
    }

    // epilogue: add bias, route to q/k (hi/lo split) or v (bf16)
    #pragma unroll
    for (int mi = 0; mi < 4; mi++) {
        int px = warp_r * 64 + mi * 16 + (lane >> 2);
        size_t pg0 = (size_t)ptile * 128 + px;
        size_t pg1 = pg0 + 8;
        #pragma unroll
        for (int ni = 0; ni < 2; ni++) {
            int c = warp_o * 16 + ni * 8 + (lane & 3) * 2;
            int o = otile * 64 + c;
            float b0, b1;
            if (o < 32)      { b0 = bq[o];      b1 = bq[o + 1]; }
            else if (o < 64) { b0 = bk[o - 32]; b1 = bk[o - 31]; }
            else             { b0 = bv[o - 64]; b1 = bv[o - 63]; }
            float v00 = acc[mi][ni][0] + b0, v01 = acc[mi][ni][1] + b1;
            float v10 = acc[mi][ni][2] + b0, v11 = acc[mi][ni][3] + b1;
            if (otile == 0) {
                uint32_t* dst = (o < 32) ? (uint32_t*)g_q64 : (uint32_t*)g_k64;
                int oo = o & 31;
                float h00 = __bfloat162float(__float2bfloat16(v00));
                float h01 = __bfloat162float(__float2bfloat16(v01));
                float h10 = __bfloat162float(__float2bfloat16(v10));
                float h11 = __bfloat162float(__float2bfloat16(v11));
                dst[pg0 * 32 + (oo >> 1)]      = packbf(h00, h01);
                dst[pg0 * 32 + 16 + (oo >> 1)] = packbf(v00 - h00, v01 - h01);
                dst[pg1 * 32 + (oo >> 1)]      = packbf(h10, h11);
                dst[pg1 * 32 + 16 + (oo >> 1)] = packbf(v10 - h10, v11 - h11);
            } else {
                int cv = o - 64;
                *(uint32_t*)(g_v + pg0 * 256 + cv) = packbf(v00, v01);
                *(uint32_t*)(g_v + pg1 * 256 + cv) = packbf(v10, v11);
            }
        }
    }
}

// ---------------------------------------------------------------------------
// Kernel 3: E = QK^T (compensated bf16 HMMA) + fused exp(E-40) -> P, row sums.
// ---------------------------------------------------------------------------
__global__ __launch_bounds__(256, 2) void egemm_kernel()
{
    __shared__ __align__(16) __nv_bfloat16 esm[2 * 128 * 72];
    __nv_bfloat16* sQ = esm;
    __nv_bfloat16* sK = esm + 128 * 72;
    const int m0 = blockIdx.x * 128, n0 = blockIdx.y * 128, b = blockIdx.z;
    const int t = threadIdx.x, lane = t & 31, wid = t >> 5;
    const int warp_r = wid >> 2, warp_c = wid & 3;

    {
        const uint4* qs = (const uint4*)(g_q64 + ((size_t)(b * NPIX + n0)) * 64);
        const uint4* ks = (const uint4*)(g_k64 + ((size_t)(b * NPIX + m0)) * 64);
        uint4* q4 = (uint4*)sQ;
        uint4* k4 = (uint4*)sK;
        #pragma unroll
        for (int i = 0; i < 4; i++) {
            int idx = i * 256 + t;
            int row = idx >> 3, ch = idx & 7;
            q4[row * 9 + ch] = qs[idx];
            k4[row * 9 + ch] = ks[idx];
        }
    }
    __syncthreads();

    float acc[4][4][4];
    #pragma unroll
    for (int mi = 0; mi < 4; mi++)
        #pragma unroll
        for (int ni = 0; ni < 4; ni++)
            #pragma unroll
            for (int i = 0; i < 4; i++) acc[mi][ni][i] = 0.0f;

    #pragma unroll
    for (int prod = 0; prod < 3; prod++) {
        const int aoff = (prod == 1) ? 32 : 0;
        const int boff = (prod == 2) ? 32 : 0;
        #pragma unroll
        for (int k16 = 0; k16 < 2; k16++) {
            const int kb = k16 * 16;
            uint32_t A[4][4];
            #pragma unroll
            for (int mi = 0; mi < 4; mi++)
                ldsm4(A[mi], s2u(sQ + (warp_r * 64 + mi * 16 + (lane & 15)) * 72
                                    + aoff + kb + ((lane >> 4) << 3)));
            uint32_t Bm[2][4];
            #pragma unroll
            for (int nj = 0; nj < 2; nj++)
                ldsm4(Bm[nj], s2u(sK + (warp_c * 32 + nj * 16 + (lane & 15)) * 72
                                     + boff + kb + ((lane >> 4) << 3)));
            #pragma unroll
            for (int mi = 0; mi < 4; mi++)
                #pragma unroll
                for (int ni = 0; ni < 4; ni++) {
                    int nj = ni >> 1, s = ni & 1;
                    mma16816(acc[mi][ni], A[mi], Bm[nj][s], Bm[nj][s + 2]);
                }
        }
    }
    __syncthreads();

    __nv_bfloat16* sS = esm;
    #pragma unroll
    for (int mi = 0; mi < 4; mi++) {
        int r0 = warp_r * 64 + mi * 16 + (lane >> 2);
        #pragma unroll
        for (int ni = 0; ni < 4; ni++) {
            int c = warp_c * 32 + ni * 8 + (lane & 3) * 2;
            float p00 = __expf(acc[mi][ni][0] - 40.0f);
            float p01 = __expf(acc[mi][ni][1] - 40.0f);
            float p10 = __expf(acc[mi][ni][2] - 40.0f);
            float p11 = __expf(acc[mi][ni][3] - 40.0f);
            *(uint32_t*)(sS + r0 * 136 + c)       = packbf(p00, p01);
            *(uint32_t*)(sS + (r0 + 8) * 136 + c) = packbf(p10, p11);
        }
    }
    __syncthreads();

    #pragma unroll
    for (int pass = 0; pass < 4; pass++) {
        int row = pass * 32 + (t >> 3), ch = t & 7;
        const uint4* srow = (const uint4*)(sS + row * 136);
        uint4 u0 = srow[ch * 2], u1 = srow[ch * 2 + 1];
        float s = 0.0f;
        const uint32_t wv[8] = {u0.x, u0.y, u0.z, u0.w, u1.x, u1.y, u1.z, u1.w};
        #pragma unroll
        for (int i = 0; i < 8; i++) {
            __nv_bfloat162 h = *(const __nv_bfloat162*)&wv[i];
            s += __bfloat162float(h.x) + __bfloat162float(h.y);
        }
        s += __shfl_xor_sync(0xffffffffu, s, 1);
        s += __shfl_xor_sync(0xffffffffu, s, 2);
        s += __shfl_xor_sync(0xffffffffu, s, 4);
        if (ch == 0) atomicAdd(&g_l[b * NPIX + n0 + row], s);
        uint4* drow = (uint4*)(g_P + ((size_t)(b * NPIX + n0 + row)) * NPIX + m0);
        drow[ch * 2] = u0;
        drow[ch * 2 + 1] = u1;
    }
}

// ---------------------------------------------------------------------------
// Kernel 4: O = P @ V  (bf16 HMMA, cp.async double buffer). Output transposed
// [b][c][n] via smem staging so the epilogue kernel reads coalesced.
// ---------------------------------------------------------------------------
#define PBUF (128 * 72)
#define VBUF (64 * 264)
#define BUFBF (PBUF + VBUF)
#define PV_SMEM (2 * BUFBF * 2)

__global__ __launch_bounds__(256, 1) void pv_kernel()
{
    extern __shared__ __align__(16) __nv_bfloat16 pvs[];
    const int n0 = blockIdx.x * 128, b = blockIdx.y;
    const int t = threadIdx.x, lane = t & 31, wid = t >> 5;
    const int warp_r = wid >> 2, warp_c = wid & 3;

    const __nv_bfloat16* pbase = g_P + ((size_t)(b * NPIX + n0)) * NPIX;
    const __nv_bfloat16* vbase = g_v + (size_t)b * NPIX * CDIM;

    float acc[4][8][4];
    #pragma unroll
    for (int mi = 0; mi < 4; mi++)
        #pragma unroll
        for (int ni = 0; ni < 8; ni++)
            #pragma unroll
            for (int i = 0; i < 4; i++) acc[mi][ni][i] = 0.0f;

    auto issue = [&](int ch, int s) {
        __nv_bfloat16* sP = pvs + s * BUFBF;
        __nv_bfloat16* sV = sP + PBUF;
        #pragma unroll
        for (int i = 0; i < 4; i++) {
            int idx = i * 256 + t;
            int row = idx >> 3, c8 = idx & 7;
            cpa16(s2u(sP + row * 72 + c8 * 8),
                  pbase + (size_t)row * NPIX + ch * 64 + c8 * 8);
        }
        #pragma unroll
        for (int i = 0; i < 8; i++) {
            int idx = i * 256 + t;
            int row = idx >> 5, c8 = idx & 31;
            cpa16(s2u(sV + row * 264 + c8 * 8),
                  vbase + (size_t)(ch * 64 + row) * CDIM + c8 * 8);
        }
        CP_COMMIT();
    };

    issue(0, 0);
    for (int ch = 0; ch < 64; ch++) {
        if (ch < 63) issue(ch + 1, (ch + 1) & 1);
        if (ch < 63) asm volatile("cp.async.wait_group 1;" ::: "memory");
        else         asm volatile("cp.async.wait_group 0;" ::: "memory");
        __syncthreads();
        __nv_bfloat16* sP = pvs + (ch & 1) * BUFBF;
        __nv_bfloat16* sV = sP + PBUF;
        #pragma unroll
        for (int k16 = 0; k16 < 4; k16++) {
            const int kb = k16 * 16;
            uint32_t A[4][4];
            #pragma unroll
            for (int mi = 0; mi < 4; mi++)
                ldsm4(A[mi], s2u(sP + (warp_r * 64 + mi * 16 + (lane & 15)) * 72
                                    + kb + ((lane >> 4) << 3)));
            uint32_t Bm[4][4];
            #pragma unroll
            for (int nj = 0; nj < 4; nj++) {
                int k = kb + (lane & 7) + ((lane >> 4) << 3);
                int n = warp_c * 64 + nj * 16 + ((lane >> 3) & 1) * 8;
                ldsm4t(Bm[nj], s2u(sV + k * 264 + n));
            }
            #pragma unroll
            for (int mi = 0; mi < 4; mi++)
                #pragma unroll
                for (int ni = 0; ni < 8; ni++) {
                    int nj = ni >> 1, s = ni & 1;
                    mma16816(acc[mi][ni], A[mi], Bm[nj][s], Bm[nj][s + 2]);
                }
        }
        __syncthreads();
    }

    // epilogue: normalize, transpose via smem, write g_o[b][c][n] coalesced
    float* sT = (float*)pvs;   // [128 c][140 px-stride]
    #pragma unroll
    for (int half = 0; half < 2; half++) {
        if ((warp_c >> 1) == half) {
            #pragma unroll
            for (int mi = 0; mi < 4; mi++) {
                int px0 = warp_r * 64 + mi * 16 + (lane >> 2);
                float li0 = 1.0f / g_l[b * NPIX + n0 + px0];
                float li1 = 1.0f / g_l[b * NPIX + n0 + px0 + 8];
                #pragma unroll
                for (int ni = 0; ni < 8; ni++) {
                    int cl = (warp_c & 1) * 64 + ni * 8 + (lane & 3) * 2;
                    sT[cl * 140 + px0]           = acc[mi][ni][0] * li0;
                    sT[(cl + 1) * 140 + px0]     = acc[mi][ni][1] * li0;
                    sT[cl * 140 + px0 + 8]       = acc[mi][ni][2] * li1;
                    sT[(cl + 1) * 140 + px0 + 8] = acc[mi][ni][3] * li1;
                }
            }
        }
        __syncthreads();
        #pragma unroll
        for (int i = 0; i < 16; i++) {
            int f4 = i * 256 + t;
            int c = f4 >> 5, col = (f4 & 31) * 4;
            float4 v = *(float4*)(sT + c * 140 + col);
            *(float4*)(g_o + ((size_t)(b * 256 + half * 128 + c)) * 4096 + n0 + col) = v;
        }
        __syncthreads();
    }
}

// ---------------------------------------------------------------------------
// Kernel 5: epilogue gamma*O + xp, depth-to-space. g_o is [b][c][n] so reads
// are 256B-coalesced segments.
// ---------------------------------------------------------------------------
__global__ __launch_bounds__(256) void epi_kernel(
    const float* __restrict__ x, const float* __restrict__ gamma,
    float* __restrict__ out)
{
    int idx = blockIdx.x * 256 + threadIdx.x;
    int w = idx & 127, h = (idx >> 7) & 127, ci = (idx >> 14) & 63, b = idx >> 20;
    int CC = (w & 1) * 128 + (h & 1) * 64 + ci;
    int n = (h >> 1) * 64 + (w >> 1);
    out[idx] = __ldg(gamma) * g_o[((size_t)(b * 256 + CC)) * 4096 + n] + x[idx];
}

// ---------------------------------------------------------------------------
extern "C" void kernel_launch(void* const* d_in, const int* in_sizes, int n_in,
                              void* d_out, int out_size)
{
    const float* x     = (const float*)d_in[0];
    const float* wq    = (const float*)d_in[1];
    const float* bq    = (const float*)d_in[2];
    const float* wk    = (const float*)d_in[3];
    const float* bk    = (const float*)d_in[4];
    const float* wv    = (const float*)d_in[5];
    const float* bv    = (const float*)d_in[6];
    const float* gamma = (const float*)d_in[7];
    float* out = (float*)d_out;
    (void)in_sizes; (void)n_in; (void)out_size;

    cudaFuncSetAttribute(projgemm_kernel, cudaFuncAttributeMaxDynamicSharedMemorySize, PG_SMEM);
    cudaFuncSetAttribute(pv_kernel,       cudaFuncAttributeMaxDynamicSharedMemorySize, PV_SMEM);

    wconv_kernel<<<80, 256>>>(wq, wk, wv);

    dim3 ggrid(2, 64, BATCH);
    gather_kernel<<<ggrid, 256>>>(x);

    dim3 pggrid(NPTOT / 128, 5);
    projgemm_kernel<<<pggrid, 256, PG_SMEM>>>(bq, bk, bv);

    dim3 egrid(NPIX / 128, NPIX / 128, BATCH);
    egemm_kernel<<<egrid, 256>>>();

    dim3 vgrid(NPIX / 128, BATCH);
    pv_kernel<<<vgrid, 256, PV_SMEM>>>();

    epi_kernel<<<(BATCH * 64 * 128 * 128) / 256, 256>>>(x, gamma, out);
}